// round 2
// baseline (speedup 1.0000x reference)
#include <cuda_runtime.h>
#include <math.h>

#define T_ 16
#define B_ 1024
#define F_ 512
#define H_ 128
#define L_ 512
#define C_ 100
// L*T = 8192

// ---------------- scratch (static device globals; no allocation allowed) -----
__device__ float g_h[T_ * B_ * H_];      // 16*1024*128   =  8 MB
__device__ float g_p[T_ * B_ * L_];      // 16*1024*512   = 32 MB
__device__ float g_mu[T_ * B_ * L_];     // 32 MB
__device__ float g_leafp[T_ * L_ * C_];  // 3.3 MB
__device__ float g_part[T_ * B_ * C_];   // 6.6 MB

__device__ __forceinline__ float sigmoidf(float x) {
    return 1.0f / (1.0f + __expf(-x));
}

// ---------------------------------------------------------------------------
// Generic batched fp32 GEMM: C[t] = act(A[t] @ B[t] + bias[t])
// 128x128 block tile, 16 k-tile, 256 threads, 8x8 microtile.
// act: 0 = relu, 1 = sigmoid
// ---------------------------------------------------------------------------
__global__ __launch_bounds__(256) void gemm_bias_act(
    const float* __restrict__ A, long sA,
    const float* __restrict__ Bm, long sB,
    const float* __restrict__ bias, long sBias,
    float* __restrict__ C, long sC,
    int M, int N, int K, int act)
{
    __shared__ float As[16][128];
    __shared__ float Bs[16][128];

    int t = blockIdx.z;
    A    += (long)t * sA;
    Bm   += (long)t * sB;
    bias += (long)t * sBias;
    C    += (long)t * sC;

    int m0 = blockIdx.x * 128;
    int n0 = blockIdx.y * 128;
    int tid = threadIdx.x;
    int tx = tid & 15;       // 0..15 -> 8 cols each
    int ty = tid >> 4;       // 0..15 -> 8 rows each

    float acc[8][8];
    #pragma unroll
    for (int i = 0; i < 8; i++)
        #pragma unroll
        for (int j = 0; j < 8; j++) acc[i][j] = 0.0f;

    for (int k0 = 0; k0 < K; k0 += 16) {
        // load A tile (128 rows x 16 k), store transposed As[k][m]
        #pragma unroll
        for (int l = 0; l < 2; l++) {
            int j = tid + l * 256;           // 0..511 float4 slots
            int row = j >> 2;
            int kc  = (j & 3) << 2;
            float4 v = *(const float4*)(A + (long)(m0 + row) * K + k0 + kc);
            As[kc + 0][row] = v.x;
            As[kc + 1][row] = v.y;
            As[kc + 2][row] = v.z;
            As[kc + 3][row] = v.w;
        }
        // load B tile (16 k x 128 n)
        #pragma unroll
        for (int l = 0; l < 2; l++) {
            int j = tid + l * 256;
            int row = j >> 5;
            int nc  = (j & 31) << 2;
            *(float4*)&Bs[row][nc] =
                *(const float4*)(Bm + (long)(k0 + row) * N + n0 + nc);
        }
        __syncthreads();

        #pragma unroll
        for (int kk = 0; kk < 16; kk++) {
            float a[8], b[8];
            *(float4*)(a + 0) = *(float4*)&As[kk][ty * 8 + 0];
            *(float4*)(a + 4) = *(float4*)&As[kk][ty * 8 + 4];
            *(float4*)(b + 0) = *(float4*)&Bs[kk][tx * 8 + 0];
            *(float4*)(b + 4) = *(float4*)&Bs[kk][tx * 8 + 4];
            #pragma unroll
            for (int i = 0; i < 8; i++)
                #pragma unroll
                for (int j = 0; j < 8; j++)
                    acc[i][j] += a[i] * b[j];
        }
        __syncthreads();
    }

    // epilogue: bias + activation
    #pragma unroll
    for (int i = 0; i < 8; i++) {
        int row = m0 + ty * 8 + i;
        float vout[8];
        #pragma unroll
        for (int j = 0; j < 8; j++) {
            int col = n0 + tx * 8 + j;
            float v = acc[i][j] + bias[col];
            vout[j] = (act == 0) ? fmaxf(v, 0.0f) : sigmoidf(v);
        }
        *(float4*)(C + (long)row * N + n0 + tx * 8 + 0) = *(float4*)(vout + 0);
        *(float4*)(C + (long)row * N + n0 + tx * 8 + 4) = *(float4*)(vout + 4);
    }
}

// ---------------------------------------------------------------------------
// Routing product: mu[t,b,l] = prod_{d=0..8} (side ? 1-p[node] : p[node])
// node = 2^d - 1 + (l >> (9-d)),  side = (l >> (8-d)) & 1
// ---------------------------------------------------------------------------
__global__ __launch_bounds__(512) void mu_kernel(const float* __restrict__ p,
                                                 float* __restrict__ mu)
{
    int b = blockIdx.x;
    int t = blockIdx.y;
    int l = threadIdx.x;
    __shared__ float ps[L_];

    long base = ((long)t * B_ + b) * L_;
    ps[l] = p[base + l];
    __syncthreads();

    float m = 1.0f;
    #pragma unroll
    for (int d = 0; d <= 8; d++) {
        int node = (1 << d) - 1 + (l >> (9 - d));
        float v = ps[node];
        m *= ((l >> (8 - d)) & 1) ? (1.0f - v) : v;
    }
    mu[base + l] = m;
}

// ---------------------------------------------------------------------------
// softmax over last axis of pi [T*L rows, C=100]; one warp per row.
// ---------------------------------------------------------------------------
__global__ __launch_bounds__(32) void softmax_kernel(const float* __restrict__ pi,
                                                     float* __restrict__ leafp)
{
    long row = blockIdx.x;
    const float* x = pi + row * C_;
    float* y = leafp + row * C_;
    int lane = threadIdx.x;

    float v[4];
    float mx = -1e30f;
    #pragma unroll
    for (int i = 0; i < 4; i++) {
        int c = lane + i * 32;
        v[i] = (c < C_) ? x[c] : -1e30f;
        mx = fmaxf(mx, v[i]);
    }
    #pragma unroll
    for (int o = 16; o > 0; o >>= 1)
        mx = fmaxf(mx, __shfl_xor_sync(0xffffffffu, mx, o));

    float s = 0.0f;
    #pragma unroll
    for (int i = 0; i < 4; i++) {
        int c = lane + i * 32;
        v[i] = (c < C_) ? expf(v[i] - mx) : 0.0f;
        s += v[i];
    }
    #pragma unroll
    for (int o = 16; o > 0; o >>= 1)
        s += __shfl_xor_sync(0xffffffffu, s, o);

    float inv = 1.0f / s;
    #pragma unroll
    for (int i = 0; i < 4; i++) {
        int c = lane + i * 32;
        if (c < C_) y[c] = v[i] * inv;
    }
}

// ---------------------------------------------------------------------------
// Final contraction per tree (deterministic split-K over trees):
// part[t][b][c] = sum_l mu[t,b,l] * leafp[t,l,c]
// 64x128 block tile (N=100 guarded), 256 threads, 4x8 microtile.
// ---------------------------------------------------------------------------
__global__ __launch_bounds__(256) void gemm_final(
    const float* __restrict__ mu, const float* __restrict__ leafp,
    float* __restrict__ part)
{
    __shared__ float As[16][64];
    __shared__ float Bs[16][128];

    int t = blockIdx.z;
    const float* A  = mu    + (long)t * B_ * L_;
    const float* Bm = leafp + (long)t * L_ * C_;
    float*       P  = part  + (long)t * B_ * C_;

    int m0 = blockIdx.x * 64;
    int tid = threadIdx.x;
    int tx = tid & 15;
    int ty = tid >> 4;

    float acc[4][8];
    #pragma unroll
    for (int i = 0; i < 4; i++)
        #pragma unroll
        for (int j = 0; j < 8; j++) acc[i][j] = 0.0f;

    for (int k0 = 0; k0 < L_; k0 += 16) {
        // A tile: 64 rows x 16 k = 256 float4 slots, one per thread
        {
            int j = tid;
            int row = j >> 2;
            int kc  = (j & 3) << 2;
            float4 v = *(const float4*)(A + (long)(m0 + row) * L_ + k0 + kc);
            As[kc + 0][row] = v.x;
            As[kc + 1][row] = v.y;
            As[kc + 2][row] = v.z;
            As[kc + 3][row] = v.w;
        }
        // B tile: 16 k x 128 n (valid n < 100, C_=100 is a multiple of 4)
        #pragma unroll
        for (int l = 0; l < 2; l++) {
            int j = tid + l * 256;
            int row = j >> 5;
            int nc  = (j & 31) << 2;
            float4 v = make_float4(0.f, 0.f, 0.f, 0.f);
            if (nc < C_)
                v = *(const float4*)(Bm + (long)(k0 + row) * C_ + nc);
            *(float4*)&Bs[row][nc] = v;
        }
        __syncthreads();

        #pragma unroll
        for (int kk = 0; kk < 16; kk++) {
            float a[4], b[8];
            *(float4*)a       = *(float4*)&As[kk][ty * 4];
            *(float4*)(b + 0) = *(float4*)&Bs[kk][tx * 8 + 0];
            *(float4*)(b + 4) = *(float4*)&Bs[kk][tx * 8 + 4];
            #pragma unroll
            for (int i = 0; i < 4; i++)
                #pragma unroll
                for (int j = 0; j < 8; j++)
                    acc[i][j] += a[i] * b[j];
        }
        __syncthreads();
    }

    #pragma unroll
    for (int i = 0; i < 4; i++) {
        int row = m0 + ty * 4 + i;
        #pragma unroll
        for (int j = 0; j < 8; j++) {
            int col = tx * 8 + j;
            if (col < C_) P[(long)row * C_ + col] = acc[i][j];
        }
    }
}

// ---------------------------------------------------------------------------
// Deterministic reduce over trees + scale + log
// ---------------------------------------------------------------------------
__global__ __launch_bounds__(256) void finalize_kernel(const float* __restrict__ part,
                                                       float* __restrict__ out)
{
    int i = blockIdx.x * 256 + threadIdx.x;
    if (i >= B_ * C_) return;
    float s = 0.0f;
    #pragma unroll
    for (int t = 0; t < T_; t++) s += part[(long)t * B_ * C_ + i];
    out[i] = logf(s * (1.0f / (float)(L_ * T_)));
}

// ---------------------------------------------------------------------------
extern "C" void kernel_launch(void* const* d_in, const int* in_sizes, int n_in,
                              void* d_out, int out_size)
{
    const float* feat = (const float*)d_in[0];   // [B, F]
    const float* W1   = (const float*)d_in[1];   // [T, F, H]
    const float* b1   = (const float*)d_in[2];   // [T, H]
    const float* W2   = (const float*)d_in[3];   // [T, H, L]
    const float* b2   = (const float*)d_in[4];   // [T, L]
    const float* pi   = (const float*)d_in[5];   // [T, L, C]
    float* out        = (float*)d_out;           // [B, C]

    void *ph, *pp, *pmu, *pleaf, *ppart;
    cudaGetSymbolAddress(&ph,    g_h);
    cudaGetSymbolAddress(&pp,    g_p);
    cudaGetSymbolAddress(&pmu,   g_mu);
    cudaGetSymbolAddress(&pleaf, g_leafp);
    cudaGetSymbolAddress(&ppart, g_part);

    // GEMM1: h[t] = relu(feat @ W1[t] + b1[t])   M=1024 N=128 K=512
    gemm_bias_act<<<dim3(B_ / 128, H_ / 128, T_), 256>>>(
        feat, 0L,
        W1, (long)F_ * H_,
        b1, (long)H_,
        (float*)ph, (long)B_ * H_,
        B_, H_, F_, /*act=*/0);

    // GEMM2: p[t] = sigmoid(h[t] @ W2[t] + b2[t])   M=1024 N=512 K=128
    gemm_bias_act<<<dim3(B_ / 128, L_ / 128, T_), 256>>>(
        (const float*)ph, (long)B_ * H_,
        W2, (long)H_ * L_,
        b2, (long)L_,
        (float*)pp, (long)B_ * L_,
        B_, L_, H_, /*act=*/1);

    // routing products
    mu_kernel<<<dim3(B_, T_), 512>>>((const float*)pp, (float*)pmu);

    // leaf distributions
    softmax_kernel<<<T_ * L_, 32>>>(pi, (float*)pleaf);

    // per-tree contraction
    gemm_final<<<dim3(B_ / 64, 1, T_), 256>>>(
        (const float*)pmu, (const float*)pleaf, (float*)ppart);

    // sum over trees, scale, log
    finalize_kernel<<<(B_ * C_ + 255) / 256, 256>>>((const float*)ppart, out);
}

// round 3
// speedup vs baseline: 1.0073x; 1.0073x over previous
#include <cuda_runtime.h>
#include <math.h>

#define T_ 16
#define B_ 1024
#define F_ 512
#define H_ 128
#define L_ 512
#define C_ 100
// L*T = 8192

// ---------------- scratch (static device globals; no allocation allowed) -----
__device__ float g_h[T_ * B_ * H_];      // 8 MB
__device__ float g_p[T_ * B_ * L_];      // 32 MB
__device__ float g_mu[T_ * B_ * L_];     // 32 MB
__device__ float g_leafp[T_ * L_ * C_];  // 3.3 MB
__device__ float g_part[T_ * B_ * C_];   // 6.6 MB

__device__ __forceinline__ float sigmoidf(float x) {
    return 1.0f / (1.0f + __expf(-x));
}

// ---------------- packed fp32x2 helpers (Blackwell FFMA2) --------------------
typedef unsigned long long u64;

__device__ __forceinline__ u64 pack2_dup(float x) {
    u64 r;
    asm("mov.b64 %0, {%1, %1};" : "=l"(r) : "f"(x));
    return r;
}
__device__ __forceinline__ void ffma2(u64& d, u64 a, u64 b) {
    asm("fma.rn.f32x2 %0, %1, %2, %3;" : "=l"(d) : "l"(a), "l"(b), "l"(d));
}
__device__ __forceinline__ void unpack2(u64 v, float& x, float& y) {
    asm("mov.b64 {%0, %1}, %2;" : "=f"(x), "=f"(y) : "l"(v));
}

// ---------------------------------------------------------------------------
// Generic batched fp32 GEMM: C[t] = act(A[t] @ B[t] + bias[t])
// 128x128 block tile, 16 k-tile, 256 threads, 8x8 microtile, FFMA2 inner loop.
// act: 0 = relu, 1 = sigmoid
// ---------------------------------------------------------------------------
__global__ __launch_bounds__(256) void gemm_bias_act(
    const float* __restrict__ A, long sA,
    const float* __restrict__ Bm, long sB,
    const float* __restrict__ bias, long sBias,
    float* __restrict__ C, long sC,
    int M, int N, int K, int act)
{
    __shared__ float As[16][128];
    __shared__ float Bs[16][128];

    int t = blockIdx.z;
    A    += (long)t * sA;
    Bm   += (long)t * sB;
    bias += (long)t * sBias;
    C    += (long)t * sC;

    int m0 = blockIdx.x * 128;
    int n0 = blockIdx.y * 128;
    int tid = threadIdx.x;
    int tx = tid & 15;       // 0..15 -> 8 cols each
    int ty = tid >> 4;       // 0..15 -> 8 rows each

    u64 acc2[8][4];
    #pragma unroll
    for (int i = 0; i < 8; i++)
        #pragma unroll
        for (int j = 0; j < 4; j++) acc2[i][j] = 0ULL;

    for (int k0 = 0; k0 < K; k0 += 16) {
        // load A tile (128 rows x 16 k), store transposed As[k][m]
        #pragma unroll
        for (int l = 0; l < 2; l++) {
            int j = tid + l * 256;           // 0..511 float4 slots
            int row = j >> 2;
            int kc  = (j & 3) << 2;
            float4 v = *(const float4*)(A + (long)(m0 + row) * K + k0 + kc);
            As[kc + 0][row] = v.x;
            As[kc + 1][row] = v.y;
            As[kc + 2][row] = v.z;
            As[kc + 3][row] = v.w;
        }
        // load B tile (16 k x 128 n)
        #pragma unroll
        for (int l = 0; l < 2; l++) {
            int j = tid + l * 256;
            int row = j >> 5;
            int nc  = (j & 31) << 2;
            *(float4*)&Bs[row][nc] =
                *(const float4*)(Bm + (long)(k0 + row) * N + n0 + nc);
        }
        __syncthreads();

        #pragma unroll
        for (int kk = 0; kk < 16; kk++) {
            float a[8];
            *(float4*)(a + 0) = *(float4*)&As[kk][ty * 8 + 0];
            *(float4*)(a + 4) = *(float4*)&As[kk][ty * 8 + 4];
            // B pairs: reinterpret 32B-aligned shared as packed f32x2
            const u64* bp = (const u64*)&Bs[kk][tx * 8];
            u64 b0 = bp[0], b1 = bp[1], b2 = bp[2], b3 = bp[3];
            #pragma unroll
            for (int i = 0; i < 8; i++) {
                u64 a2 = pack2_dup(a[i]);
                ffma2(acc2[i][0], a2, b0);
                ffma2(acc2[i][1], a2, b1);
                ffma2(acc2[i][2], a2, b2);
                ffma2(acc2[i][3], a2, b3);
            }
        }
        __syncthreads();
    }

    // epilogue: bias + activation
    #pragma unroll
    for (int i = 0; i < 8; i++) {
        int row = m0 + ty * 8 + i;
        float vout[8];
        #pragma unroll
        for (int j = 0; j < 4; j++) {
            float x, y;
            unpack2(acc2[i][j], x, y);
            vout[j * 2 + 0] = x;
            vout[j * 2 + 1] = y;
        }
        #pragma unroll
        for (int j = 0; j < 8; j++) {
            int col = n0 + tx * 8 + j;
            float v = vout[j] + bias[col];
            vout[j] = (act == 0) ? fmaxf(v, 0.0f) : sigmoidf(v);
        }
        *(float4*)(C + (long)row * N + n0 + tx * 8 + 0) = *(float4*)(vout + 0);
        *(float4*)(C + (long)row * N + n0 + tx * 8 + 4) = *(float4*)(vout + 4);
    }
}

// ---------------------------------------------------------------------------
// Routing product: mu[t,b,l] = prod_{d=0..8} (side ? 1-p[node] : p[node])
// ---------------------------------------------------------------------------
__global__ __launch_bounds__(512) void mu_kernel(const float* __restrict__ p,
                                                 float* __restrict__ mu)
{
    int b = blockIdx.x;
    int t = blockIdx.y;
    int l = threadIdx.x;
    __shared__ float ps[L_];

    long base = ((long)t * B_ + b) * L_;
    ps[l] = p[base + l];
    __syncthreads();

    float m = 1.0f;
    #pragma unroll
    for (int d = 0; d <= 8; d++) {
        int node = (1 << d) - 1 + (l >> (9 - d));
        float v = ps[node];
        m *= ((l >> (8 - d)) & 1) ? (1.0f - v) : v;
    }
    mu[base + l] = m;
}

// ---------------------------------------------------------------------------
// softmax over last axis of pi [T*L rows, C=100]; one warp per row, 8 rows/blk
// ---------------------------------------------------------------------------
__global__ __launch_bounds__(256) void softmax_kernel(const float* __restrict__ pi,
                                                      float* __restrict__ leafp)
{
    long row = (long)blockIdx.x * 8 + (threadIdx.x >> 5);
    const float* x = pi + row * C_;
    float* y = leafp + row * C_;
    int lane = threadIdx.x & 31;

    float v[4];
    float mx = -1e30f;
    #pragma unroll
    for (int i = 0; i < 4; i++) {
        int c = lane + i * 32;
        v[i] = (c < C_) ? x[c] : -1e30f;
        mx = fmaxf(mx, v[i]);
    }
    #pragma unroll
    for (int o = 16; o > 0; o >>= 1)
        mx = fmaxf(mx, __shfl_xor_sync(0xffffffffu, mx, o));

    float s = 0.0f;
    #pragma unroll
    for (int i = 0; i < 4; i++) {
        int c = lane + i * 32;
        v[i] = (c < C_) ? expf(v[i] - mx) : 0.0f;
        s += v[i];
    }
    #pragma unroll
    for (int o = 16; o > 0; o >>= 1)
        s += __shfl_xor_sync(0xffffffffu, s, o);

    float inv = 1.0f / s;
    #pragma unroll
    for (int i = 0; i < 4; i++) {
        int c = lane + i * 32;
        if (c < C_) y[c] = v[i] * inv;
    }
}

// ---------------------------------------------------------------------------
// Final contraction per tree (deterministic split-K over trees):
// part[t][b][c] = sum_l mu[t,b,l] * leafp[t,l,c]
// 64x128 block tile (N=100 guarded), 256 threads, 4x8 microtile, FFMA2.
// ---------------------------------------------------------------------------
__global__ __launch_bounds__(256) void gemm_final(
    const float* __restrict__ mu, const float* __restrict__ leafp,
    float* __restrict__ part)
{
    __shared__ float As[16][64];
    __shared__ float Bs[16][128];

    int t = blockIdx.z;
    const float* A  = mu    + (long)t * B_ * L_;
    const float* Bm = leafp + (long)t * L_ * C_;
    float*       P  = part  + (long)t * B_ * C_;

    int m0 = blockIdx.x * 64;
    int tid = threadIdx.x;
    int tx = tid & 15;
    int ty = tid >> 4;

    u64 acc2[4][4];
    #pragma unroll
    for (int i = 0; i < 4; i++)
        #pragma unroll
        for (int j = 0; j < 4; j++) acc2[i][j] = 0ULL;

    for (int k0 = 0; k0 < L_; k0 += 16) {
        // A tile: 64 rows x 16 k = 256 float4 slots, one per thread
        {
            int j = tid;
            int row = j >> 2;
            int kc  = (j & 3) << 2;
            float4 v = *(const float4*)(A + (long)(m0 + row) * L_ + k0 + kc);
            As[kc + 0][row] = v.x;
            As[kc + 1][row] = v.y;
            As[kc + 2][row] = v.z;
            As[kc + 3][row] = v.w;
        }
        // B tile: 16 k x 128 n (valid n < 100, C_=100 is a multiple of 4)
        #pragma unroll
        for (int l = 0; l < 2; l++) {
            int j = tid + l * 256;
            int row = j >> 5;
            int nc  = (j & 31) << 2;
            float4 v = make_float4(0.f, 0.f, 0.f, 0.f);
            if (nc < C_)
                v = *(const float4*)(Bm + (long)(k0 + row) * C_ + nc);
            *(float4*)&Bs[row][nc] = v;
        }
        __syncthreads();

        #pragma unroll
        for (int kk = 0; kk < 16; kk++) {
            float a[4];
            *(float4*)a = *(float4*)&As[kk][ty * 4];
            const u64* bp = (const u64*)&Bs[kk][tx * 8];
            u64 b0 = bp[0], b1 = bp[1], b2 = bp[2], b3 = bp[3];
            #pragma unroll
            for (int i = 0; i < 4; i++) {
                u64 a2 = pack2_dup(a[i]);
                ffma2(acc2[i][0], a2, b0);
                ffma2(acc2[i][1], a2, b1);
                ffma2(acc2[i][2], a2, b2);
                ffma2(acc2[i][3], a2, b3);
            }
        }
        __syncthreads();
    }

    #pragma unroll
    for (int i = 0; i < 4; i++) {
        int row = m0 + ty * 4 + i;
        float vout[8];
        #pragma unroll
        for (int j = 0; j < 4; j++)
            unpack2(acc2[i][j], vout[j * 2], vout[j * 2 + 1]);
        #pragma unroll
        for (int j = 0; j < 8; j++) {
            int col = tx * 8 + j;
            if (col < C_) P[(long)row * C_ + col] = vout[j];
        }
    }
}

// ---------------------------------------------------------------------------
// Deterministic reduce over trees + scale + log
// ---------------------------------------------------------------------------
__global__ __launch_bounds__(256) void finalize_kernel(const float* __restrict__ part,
                                                       float* __restrict__ out)
{
    int i = blockIdx.x * 256 + threadIdx.x;
    if (i >= B_ * C_) return;
    float s = 0.0f;
    #pragma unroll
    for (int t = 0; t < T_; t++) s += part[(long)t * B_ * C_ + i];
    out[i] = logf(s * (1.0f / (float)(L_ * T_)));
}

// ---------------------------------------------------------------------------
extern "C" void kernel_launch(void* const* d_in, const int* in_sizes, int n_in,
                              void* d_out, int out_size)
{
    const float* feat = (const float*)d_in[0];   // [B, F]
    const float* W1   = (const float*)d_in[1];   // [T, F, H]
    const float* b1   = (const float*)d_in[2];   // [T, H]
    const float* W2   = (const float*)d_in[3];   // [T, H, L]
    const float* b2   = (const float*)d_in[4];   // [T, L]
    const float* pi   = (const float*)d_in[5];   // [T, L, C]
    float* out        = (float*)d_out;           // [B, C]

    void *ph, *pp, *pmu, *pleaf, *ppart;
    cudaGetSymbolAddress(&ph,    g_h);
    cudaGetSymbolAddress(&pp,    g_p);
    cudaGetSymbolAddress(&pmu,   g_mu);
    cudaGetSymbolAddress(&pleaf, g_leafp);
    cudaGetSymbolAddress(&ppart, g_part);

    // GEMM1: h[t] = relu(feat @ W1[t] + b1[t])   M=1024 N=128 K=512
    gemm_bias_act<<<dim3(B_ / 128, H_ / 128, T_), 256>>>(
        feat, 0L,
        W1, (long)F_ * H_,
        b1, (long)H_,
        (float*)ph, (long)B_ * H_,
        B_, H_, F_, /*act=*/0);

    // GEMM2: p[t] = sigmoid(h[t] @ W2[t] + b2[t])   M=1024 N=512 K=128
    gemm_bias_act<<<dim3(B_ / 128, L_ / 128, T_), 256>>>(
        (const float*)ph, (long)B_ * H_,
        W2, (long)H_ * L_,
        b2, (long)L_,
        (float*)pp, (long)B_ * L_,
        B_, L_, H_, /*act=*/1);

    // routing products
    mu_kernel<<<dim3(B_, T_), 512>>>((const float*)pp, (float*)pmu);

    // leaf distributions
    softmax_kernel<<<T_ * L_ / 8, 256>>>(pi, (float*)pleaf);

    // per-tree contraction
    gemm_final<<<dim3(B_ / 64, 1, T_), 256>>>(
        (const float*)pmu, (const float*)pleaf, (float*)ppart);

    // sum over trees, scale, log
    finalize_kernel<<<(B_ * C_ + 255) / 256, 256>>>((const float*)ppart, out);
}

// round 8
// speedup vs baseline: 2.7622x; 2.7422x over previous
#include <cuda_runtime.h>
#include <cuda_bf16.h>
#include <math.h>
#include <stdint.h>

#define T_ 16
#define B_ 1024
#define F_ 512
#define H_ 128
#define L_ 512
#define C_ 100
#define CP_ 128   // classes padded to 128 for the tensor GEMM

// ---------------- scratch (static device globals; zero-initialized) ---------
__device__ __nv_bfloat16 g_featb[B_ * F_];        // 1 MB
__device__ __nv_bfloat16 g_w1t[T_ * H_ * F_];     // 2 MB  (W1^T per tree: [H][F])
__device__ __nv_bfloat16 g_w2t[T_ * L_ * H_];     // 2 MB  (W2^T per tree: [L][H])
__device__ __nv_bfloat16 g_hb[T_ * B_ * H_];      // 4 MB
__device__ float         g_p[T_ * B_ * L_];       // 32 MB
__device__ __nv_bfloat16 g_mub[T_ * B_ * L_];     // 16 MB
__device__ __nv_bfloat16 g_lpT[T_ * CP_ * L_];    // 2 MB (rows >= C_ stay 0 forever)
__device__ float         g_part[T_ * B_ * C_];    // 6.6 MB

__device__ __forceinline__ float sigmoidf(float x) {
    return 1.0f / (1.0f + __expf(-x));
}

__device__ __forceinline__ uint32_t smem_u32(const void* p) {
    uint32_t a;
    asm("{ .reg .u64 t; cvta.to.shared.u64 t, %1; cvt.u32.u64 %0, t; }"
        : "=r"(a) : "l"(p));
    return a;
}

// swizzled byte offset inside a [128 rows x 128 bytes] smem tile
__device__ __forceinline__ uint32_t swz(int row, int colBytes) {
    return (uint32_t)(row * 128 + (colBytes ^ ((row & 7) << 4)));
}

__device__ __forceinline__ void ldsm_x4(uint32_t& r0, uint32_t& r1,
                                        uint32_t& r2, uint32_t& r3, uint32_t addr) {
    asm volatile("ldmatrix.sync.aligned.m8n8.x4.shared.b16 {%0,%1,%2,%3}, [%4];"
        : "=r"(r0), "=r"(r1), "=r"(r2), "=r"(r3) : "r"(addr) : "memory");
}

__device__ __forceinline__ void mma16816(float* c, const uint32_t* a, const uint32_t* b) {
    asm volatile(
        "mma.sync.aligned.m16n8k16.row.col.f32.bf16.bf16.f32 "
        "{%0,%1,%2,%3}, {%4,%5,%6,%7}, {%8,%9}, {%0,%1,%2,%3};"
        : "+f"(c[0]), "+f"(c[1]), "+f"(c[2]), "+f"(c[3])
        : "r"(a[0]), "r"(a[1]), "r"(a[2]), "r"(a[3]), "r"(b[0]), "r"(b[1]));
}

// ===========================================================================
// HMMA batched GEMM:  D[128 x Ntile=128] = A[128,K] @ Bw[128,K]^T  (bf16, f32 acc)
// A: [t][M][K] bf16 row-major.  Bw: [t][N][K] bf16 row-major (i.e. B^T).
// mode 0: out = bf16( relu(D + bias) )      (GEMM1 -> g_hb)
// mode 1: out = f32 ( sigmoid(D + bias) )   (GEMM2 -> g_p)
// mode 2: out = f32 ( D ), cols < C_ only   (final -> g_part, row stride C_)
// ===========================================================================
__global__ __launch_bounds__(256) void gemm_tc(
    const __nv_bfloat16* __restrict__ A, long strideAt,
    const __nv_bfloat16* __restrict__ Bw, long strideBt,
    const float* __restrict__ bias, long strideBiasT,
    void* __restrict__ Cout, long strideCt,
    int K, int Nfull, int mode)
{
    __shared__ __align__(128) uint8_t smA[128 * 128];   // 128 rows x 64 bf16
    __shared__ __align__(128) uint8_t smB[128 * 128];
    __shared__ float sBias[128];

    int tid = threadIdx.x;
    int wid = tid >> 5;
    int lane = tid & 31;
    int t = blockIdx.z;
    int m0 = blockIdx.x * 128;
    int n0 = blockIdx.y * 128;

    const __nv_bfloat16* Ap = A + (long)t * strideAt + (long)m0 * K;
    const __nv_bfloat16* Bp = Bw + (long)t * strideBt + (long)n0 * K;

    if (tid < 128)
        sBias[tid] = (mode < 2) ? bias[(long)t * strideBiasT + n0 + tid] : 0.0f;

    int wm0 = (wid & 1) * 64;    // warp m-origin within tile
    int wn0 = (wid >> 1) * 32;   // warp n-origin within tile

    uint32_t baseA = smem_u32(smA);
    uint32_t baseB = smem_u32(smB);

    // ldmatrix lane geometry (byte addresses into the swizzled tiles)
    int aRow = wm0 + (lane & 15);
    int aK   = (lane >> 4) * 16;                     // byte offset of k-half
    uint32_t aRowBase = baseA + aRow * 128;
    uint32_t aXor = (aRow & 7) << 4;

    int bRow = wn0 + (lane & 7) + ((lane >> 4) & 1) * 8;
    int bK   = ((lane >> 3) & 1) * 16;
    uint32_t bRowBase = baseB + bRow * 128;
    uint32_t bXor = (bRow & 7) << 4;

    float acc[4][4][4];
    #pragma unroll
    for (int mt = 0; mt < 4; mt++)
        #pragma unroll
        for (int nt = 0; nt < 4; nt++)
            #pragma unroll
            for (int e = 0; e < 4; e++) acc[mt][nt][e] = 0.0f;

    int nch = K >> 6;                                // K-chunks of 64
    for (int ch = 0; ch < nch; ch++) {
        int k0 = ch << 6;
        // global -> smem: 128 rows x 64 bf16 each, swizzled uint4 stores
        #pragma unroll
        for (int l = 0; l < 4; l++) {
            int j = tid + l * 256;                   // 0..1023
            int row = j >> 3;
            int cb = (j & 7) * 16;                   // byte col
            uint4 va = *(const uint4*)(Ap + (long)row * K + k0 + (cb >> 1));
            uint4 vb = *(const uint4*)(Bp + (long)row * K + k0 + (cb >> 1));
            uint32_t off = swz(row, cb);
            *(uint4*)(smA + off) = va;
            *(uint4*)(smB + off) = vb;
        }
        __syncthreads();

        #pragma unroll
        for (int kk = 0; kk < 4; kk++) {             // 4 x k16 steps
            int kb = kk * 32;                        // byte offset of k16
            uint32_t aF[4][4], bF[2][4];
            #pragma unroll
            for (int mt = 0; mt < 4; mt++)
                ldsm_x4(aF[mt][0], aF[mt][1], aF[mt][2], aF[mt][3],
                        aRowBase + mt * (16 * 128) + ((kb + aK) ^ aXor));
            #pragma unroll
            for (int ntp = 0; ntp < 2; ntp++)
                ldsm_x4(bF[ntp][0], bF[ntp][1], bF[ntp][2], bF[ntp][3],
                        bRowBase + ntp * (16 * 128) + ((kb + bK) ^ bXor));
            #pragma unroll
            for (int mt = 0; mt < 4; mt++)
                #pragma unroll
                for (int nt = 0; nt < 4; nt++)
                    mma16816(acc[mt][nt], aF[mt], &bF[nt >> 1][(nt & 1) * 2]);
        }
        __syncthreads();
    }

    // ---------------- epilogue (fragment layout: c0,c1 row r, c2,c3 row r+8) --
    int rIn = lane >> 2;           // 0..7
    int cIn = (lane & 3) * 2;      // 0,2,4,6
    #pragma unroll
    for (int mt = 0; mt < 4; mt++) {
        long rowLo = m0 + wm0 + mt * 16 + rIn;
        long rowHi = rowLo + 8;
        #pragma unroll
        for (int nt = 0; nt < 4; nt++) {
            int col = wn0 + nt * 8 + cIn;            // 0..127 within tile
            float b0 = sBias[col], b1 = sBias[col + 1];
            float v0 = acc[mt][nt][0] + b0, v1 = acc[mt][nt][1] + b1;
            float v2 = acc[mt][nt][2] + b0, v3 = acc[mt][nt][3] + b1;
            if (mode == 0) {
                __nv_bfloat16* o = (__nv_bfloat16*)Cout + (long)t * strideCt;
                *(__nv_bfloat162*)(o + rowLo * Nfull + n0 + col) =
                    __floats2bfloat162_rn(fmaxf(v0, 0.f), fmaxf(v1, 0.f));
                *(__nv_bfloat162*)(o + rowHi * Nfull + n0 + col) =
                    __floats2bfloat162_rn(fmaxf(v2, 0.f), fmaxf(v3, 0.f));
            } else if (mode == 1) {
                float* o = (float*)Cout + (long)t * strideCt;
                *(float2*)(o + rowLo * Nfull + n0 + col) =
                    make_float2(sigmoidf(v0), sigmoidf(v1));
                *(float2*)(o + rowHi * Nfull + n0 + col) =
                    make_float2(sigmoidf(v2), sigmoidf(v3));
            } else {
                if (col < C_) {
                    float* o = (float*)Cout + (long)t * strideCt;
                    *(float2*)(o + rowLo * C_ + col) = make_float2(v0, v1);
                    *(float2*)(o + rowHi * C_ + col) = make_float2(v2, v3);
                }
            }
        }
    }
}

// ---------------------------------------------------------------------------
// elementwise fp32 -> bf16
// ---------------------------------------------------------------------------
__global__ __launch_bounds__(256) void conv_bf16(const float* __restrict__ in,
                                                 __nv_bfloat16* __restrict__ out,
                                                 int n)
{
    int i = blockIdx.x * 256 + threadIdx.x;
    if (i < n) out[i] = __float2bfloat16(in[i]);
}

// ---------------------------------------------------------------------------
// batched transpose + convert: in[t][R][Cc] f32  ->  out[t][Cc][R] bf16
// ---------------------------------------------------------------------------
__global__ __launch_bounds__(256) void transpose_bf16(const float* __restrict__ in,
                                                      __nv_bfloat16* __restrict__ out,
                                                      int R, int Cc)
{
    __shared__ float tile[32][33];
    int t = blockIdx.z;
    in  += (long)t * R * Cc;
    out += (long)t * R * Cc;
    int x = blockIdx.x * 32 + threadIdx.x;
    int y0 = blockIdx.y * 32;
    #pragma unroll
    for (int j = threadIdx.y; j < 32; j += 8)
        tile[j][threadIdx.x] = in[(long)(y0 + j) * Cc + x];
    __syncthreads();
    int xo = y0 + threadIdx.x;
    int yo0 = blockIdx.x * 32;
    #pragma unroll
    for (int j = threadIdx.y; j < 32; j += 8)
        out[(long)(yo0 + j) * R + xo] = __float2bfloat16(tile[threadIdx.x][j]);
}

// ---------------------------------------------------------------------------
// Routing product (fp32 math, bf16 output for the tensor GEMM)
// ---------------------------------------------------------------------------
__global__ __launch_bounds__(512) void mu_kernel(const float* __restrict__ p,
                                                 __nv_bfloat16* __restrict__ mub)
{
    int b = blockIdx.x;
    int t = blockIdx.y;
    int l = threadIdx.x;
    __shared__ float ps[L_];

    long base = ((long)t * B_ + b) * L_;
    ps[l] = p[base + l];
    __syncthreads();

    float m = 1.0f;
    #pragma unroll
    for (int d = 0; d <= 8; d++) {
        int node = (1 << d) - 1 + (l >> (9 - d));
        float v = ps[node];
        m *= ((l >> (8 - d)) & 1) ? (1.0f - v) : v;
    }
    mub[base + l] = __float2bfloat16(m);
}

// ---------------------------------------------------------------------------
// softmax over classes; writes TRANSPOSED bf16: g_lpT[t][c][l]
// ---------------------------------------------------------------------------
__global__ __launch_bounds__(256) void softmaxT_kernel(const float* __restrict__ pi,
                                                       __nv_bfloat16* __restrict__ lpT)
{
    long row = (long)blockIdx.x * 8 + (threadIdx.x >> 5);   // t*L + l
    int t = (int)(row >> 9);
    int l = (int)(row & (L_ - 1));
    const float* x = pi + row * C_;
    int lane = threadIdx.x & 31;

    float v[4];
    float mx = -1e30f;
    #pragma unroll
    for (int i = 0; i < 4; i++) {
        int c = lane + i * 32;
        v[i] = (c < C_) ? x[c] : -1e30f;
        mx = fmaxf(mx, v[i]);
    }
    #pragma unroll
    for (int o = 16; o > 0; o >>= 1)
        mx = fmaxf(mx, __shfl_xor_sync(0xffffffffu, mx, o));

    float s = 0.0f;
    #pragma unroll
    for (int i = 0; i < 4; i++) {
        int c = lane + i * 32;
        v[i] = (c < C_) ? expf(v[i] - mx) : 0.0f;
        s += v[i];
    }
    #pragma unroll
    for (int o = 16; o > 0; o >>= 1)
        s += __shfl_xor_sync(0xffffffffu, s, o);

    float inv = 1.0f / s;
    __nv_bfloat16* yt = lpT + (long)t * CP_ * L_ + l;
    #pragma unroll
    for (int i = 0; i < 4; i++) {
        int c = lane + i * 32;
        if (c < C_) yt[(long)c * L_] = __float2bfloat16(v[i] * inv);
    }
}

// ---------------------------------------------------------------------------
// Deterministic reduce over trees + scale + log
// ---------------------------------------------------------------------------
__global__ __launch_bounds__(256) void finalize_kernel(const float* __restrict__ part,
                                                       float* __restrict__ out)
{
    int i = blockIdx.x * 256 + threadIdx.x;
    if (i >= B_ * C_) return;
    float s = 0.0f;
    #pragma unroll
    for (int t = 0; t < T_; t++) s += part[(long)t * B_ * C_ + i];
    out[i] = logf(s * (1.0f / (float)(L_ * T_)));
}

// ---------------------------------------------------------------------------
extern "C" void kernel_launch(void* const* d_in, const int* in_sizes, int n_in,
                              void* d_out, int out_size)
{
    const float* feat = (const float*)d_in[0];   // [B, F]
    const float* W1   = (const float*)d_in[1];   // [T, F, H]
    const float* b1   = (const float*)d_in[2];   // [T, H]
    const float* W2   = (const float*)d_in[3];   // [T, H, L]
    const float* b2   = (const float*)d_in[4];   // [T, L]
    const float* pi   = (const float*)d_in[5];   // [T, L, C]
    float* out        = (float*)d_out;           // [B, C]

    void *pfb, *pw1t, *pw2t, *phb, *pp, *pmub, *plpT, *ppart;
    cudaGetSymbolAddress(&pfb,   g_featb);
    cudaGetSymbolAddress(&pw1t,  g_w1t);
    cudaGetSymbolAddress(&pw2t,  g_w2t);
    cudaGetSymbolAddress(&phb,   g_hb);
    cudaGetSymbolAddress(&pp,    g_p);
    cudaGetSymbolAddress(&pmub,  g_mub);
    cudaGetSymbolAddress(&plpT,  g_lpT);
    cudaGetSymbolAddress(&ppart, g_part);

    // operand prep
    conv_bf16<<<(B_ * F_ + 255) / 256, 256>>>(feat, (__nv_bfloat16*)pfb, B_ * F_);
    transpose_bf16<<<dim3(H_ / 32, F_ / 32, T_), dim3(32, 8)>>>(
        W1, (__nv_bfloat16*)pw1t, F_, H_);
    transpose_bf16<<<dim3(L_ / 32, H_ / 32, T_), dim3(32, 8)>>>(
        W2, (__nv_bfloat16*)pw2t, H_, L_);
    softmaxT_kernel<<<T_ * L_ / 8, 256>>>(pi, (__nv_bfloat16*)plpT);

    // GEMM1: h = relu(feat @ W1 + b1)  M=1024 N=128 K=512
    gemm_tc<<<dim3(8, 1, T_), 256>>>(
        (const __nv_bfloat16*)pfb, 0L,
        (const __nv_bfloat16*)pw1t, (long)H_ * F_,
        b1, (long)H_,
        phb, (long)B_ * H_,
        F_, H_, /*mode=*/0);

    // GEMM2: p = sigmoid(h @ W2 + b2)  M=1024 N=512 K=128
    gemm_tc<<<dim3(8, 4, T_), 256>>>(
        (const __nv_bfloat16*)phb, (long)B_ * H_,
        (const __nv_bfloat16*)pw2t, (long)L_ * H_,
        b2, (long)L_,
        pp, (long)B_ * L_,
        H_, L_, /*mode=*/1);

    // routing products (fp32 in, bf16 out)
    mu_kernel<<<dim3(B_, T_), 512>>>((const float*)pp, (__nv_bfloat16*)pmub);

    // final contraction per tree: part[t] = mu[t] @ leafpT[t]^T
    gemm_tc<<<dim3(8, 1, T_), 256>>>(
        (const __nv_bfloat16*)pmub, (long)B_ * L_,
        (const __nv_bfloat16*)plpT, (long)CP_ * L_,
        b1 /*unused in mode 2*/, 0L,
        ppart, (long)B_ * C_,
        L_, 0, /*mode=*/2);

    // sum over trees, scale, log
    finalize_kernel<<<(B_ * C_ + 255) / 256, 256>>>((const float*)ppart, out);
}

// round 13
// speedup vs baseline: 2.8946x; 1.0479x over previous
#include <cuda_runtime.h>
#include <cuda_bf16.h>
#include <math.h>
#include <stdint.h>

#define T_ 16
#define B_ 1024
#define F_ 512
#define H_ 128
#define L_ 512
#define C_ 100
#define CP_ 128   // classes padded to 128 for the tensor GEMM

// ---------------- scratch (static device globals; zero-initialized) ---------
__device__ __nv_bfloat16 g_featb[B_ * F_];        // 1 MB
__device__ __nv_bfloat16 g_w1t[T_ * H_ * F_];     // 2 MB  (W1^T per tree: [H][F])
__device__ __nv_bfloat16 g_w2t[T_ * L_ * H_];     // 2 MB  (W2^T per tree: [L][H])
__device__ __nv_bfloat16 g_hb[T_ * B_ * H_];      // 4 MB
__device__ __nv_bfloat16 g_pb[T_ * B_ * L_];      // 16 MB (bf16 sigmoid output)
__device__ __nv_bfloat16 g_mub[T_ * B_ * L_];     // 16 MB
__device__ __nv_bfloat16 g_lpT[T_ * CP_ * L_];    // 2 MB (rows >= C_ stay 0 forever)
__device__ float         g_part[T_ * B_ * C_];    // 6.6 MB

__device__ __forceinline__ float sigmoidf(float x) {
    return 1.0f / (1.0f + __expf(-x));
}

__device__ __forceinline__ uint32_t smem_u32(const void* p) {
    uint32_t a;
    asm("{ .reg .u64 t; cvta.to.shared.u64 t, %1; cvt.u32.u64 %0, t; }"
        : "=r"(a) : "l"(p));
    return a;
}

// swizzled byte offset inside a [128 rows x 128 bytes] smem tile
__device__ __forceinline__ uint32_t swz(int row, int colBytes) {
    return (uint32_t)(row * 128 + (colBytes ^ ((row & 7) << 4)));
}

__device__ __forceinline__ void cp_async16(uint32_t dst, const void* src) {
    asm volatile("cp.async.cg.shared.global [%0], [%1], 16;"
        :: "r"(dst), "l"(src) : "memory");
}
#define CP_ASYNC_WAIT_ALL() \
    asm volatile("cp.async.wait_all;" ::: "memory")

__device__ __forceinline__ void ldsm_x4(uint32_t& r0, uint32_t& r1,
                                        uint32_t& r2, uint32_t& r3, uint32_t addr) {
    asm volatile("ldmatrix.sync.aligned.m8n8.x4.shared.b16 {%0,%1,%2,%3}, [%4];"
        : "=r"(r0), "=r"(r1), "=r"(r2), "=r"(r3) : "r"(addr) : "memory");
}

__device__ __forceinline__ void mma16816(float* c, const uint32_t* a, const uint32_t* b) {
    asm volatile(
        "mma.sync.aligned.m16n8k16.row.col.f32.bf16.bf16.f32 "
        "{%0,%1,%2,%3}, {%4,%5,%6,%7}, {%8,%9}, {%0,%1,%2,%3};"
        : "+f"(c[0]), "+f"(c[1]), "+f"(c[2]), "+f"(c[3])
        : "r"(a[0]), "r"(a[1]), "r"(a[2]), "r"(a[3]), "r"(b[0]), "r"(b[1]));
}

// ===========================================================================
// HMMA batched GEMM:  D[128 x 128] = A[128,K] @ Bw[128,K]^T  (bf16, f32 acc)
// A: [t][M][K] bf16 row-major.  Bw: [t][N][K] bf16 row-major (i.e. B^T).
// mode 0: out = bf16( relu(D + bias) )      (GEMM1 -> g_hb)
// mode 1: out = bf16( sigmoid(D + bias) )   (GEMM2 -> g_pb)
// mode 2: out = f32 ( D ), cols < C_ only   (final -> g_part, row stride C_)
// ===========================================================================
__global__ __launch_bounds__(256) void gemm_tc(
    const __nv_bfloat16* __restrict__ A, long strideAt,
    const __nv_bfloat16* __restrict__ Bw, long strideBt,
    const float* __restrict__ bias, long strideBiasT,
    void* __restrict__ Cout, long strideCt,
    int K, int Nfull, int mode)
{
    __shared__ __align__(128) uint8_t smA[128 * 128];   // 128 rows x 64 bf16
    __shared__ __align__(128) uint8_t smB[128 * 128];
    __shared__ float sBias[128];

    int tid = threadIdx.x;
    int wid = tid >> 5;
    int lane = tid & 31;
    int t = blockIdx.z;
    int m0 = blockIdx.x * 128;
    int n0 = blockIdx.y * 128;

    const __nv_bfloat16* Ap = A + (long)t * strideAt + (long)m0 * K;
    const __nv_bfloat16* Bp = Bw + (long)t * strideBt + (long)n0 * K;

    if (tid < 128)
        sBias[tid] = (mode < 2) ? bias[(long)t * strideBiasT + n0 + tid] : 0.0f;

    int wm0 = (wid & 1) * 64;    // warp m-origin within tile
    int wn0 = (wid >> 1) * 32;   // warp n-origin within tile

    uint32_t baseA = smem_u32(smA);
    uint32_t baseB = smem_u32(smB);

    // ldmatrix lane geometry (byte addresses into the swizzled tiles)
    int aRow = wm0 + (lane & 15);
    int aK   = (lane >> 4) * 16;                     // byte offset of k-half
    uint32_t aRowBase = baseA + aRow * 128;
    uint32_t aXor = (aRow & 7) << 4;

    int bRow = wn0 + (lane & 7) + ((lane >> 4) & 1) * 8;
    int bK   = ((lane >> 3) & 1) * 16;
    uint32_t bRowBase = baseB + bRow * 128;
    uint32_t bXor = (bRow & 7) << 4;

    // per-thread cp.async geometry: 2 threads per row, each covers 4x16B
    int ldRow = tid >> 1;                 // 0..127
    int ldCb  = (tid & 1) * 16;           // byte col of first 16B granule

    float acc[4][4][4];
    #pragma unroll
    for (int mt = 0; mt < 4; mt++)
        #pragma unroll
        for (int nt = 0; nt < 4; nt++)
            #pragma unroll
            for (int e = 0; e < 4; e++) acc[mt][nt][e] = 0.0f;

    int nch = K >> 6;                                // K-chunks of 64
    for (int ch = 0; ch < nch; ch++) {
        int k0 = ch << 6;
        // global -> smem via cp.async: FULL row coverage, 4 granules/thread/tile
        // cb = ldCb + l*32 for l=0..3 -> even thread {0,32,64,96}, odd {16,48,80,112}
        #pragma unroll
        for (int l = 0; l < 4; l++) {
            int cb = ldCb + l * 32;
            uint32_t off = swz(ldRow, cb);
            cp_async16(baseA + off, Ap + (long)ldRow * K + k0 + (cb >> 1));
            cp_async16(baseB + off, Bp + (long)ldRow * K + k0 + (cb >> 1));
        }
        CP_ASYNC_WAIT_ALL();
        __syncthreads();

        #pragma unroll
        for (int kk = 0; kk < 4; kk++) {             // 4 x k16 steps
            int kb = kk * 32;                        // byte offset of k16
            uint32_t aF[4][4], bF[2][4];
            #pragma unroll
            for (int mt = 0; mt < 4; mt++)
                ldsm_x4(aF[mt][0], aF[mt][1], aF[mt][2], aF[mt][3],
                        aRowBase + mt * (16 * 128) + ((kb + aK) ^ aXor));
            #pragma unroll
            for (int ntp = 0; ntp < 2; ntp++)
                ldsm_x4(bF[ntp][0], bF[ntp][1], bF[ntp][2], bF[ntp][3],
                        bRowBase + ntp * (16 * 128) + ((kb + bK) ^ bXor));
            #pragma unroll
            for (int mt = 0; mt < 4; mt++)
                #pragma unroll
                for (int nt = 0; nt < 4; nt++)
                    mma16816(acc[mt][nt], aF[mt], &bF[nt >> 1][(nt & 1) * 2]);
        }
        __syncthreads();
    }

    // ---------------- epilogue (fragment layout: c0,c1 row r, c2,c3 row r+8) --
    int rIn = lane >> 2;           // 0..7
    int cIn = (lane & 3) * 2;      // 0,2,4,6
    #pragma unroll
    for (int mt = 0; mt < 4; mt++) {
        long rowLo = m0 + wm0 + mt * 16 + rIn;
        long rowHi = rowLo + 8;
        #pragma unroll
        for (int nt = 0; nt < 4; nt++) {
            int col = wn0 + nt * 8 + cIn;            // 0..127 within tile
            float b0 = sBias[col], b1 = sBias[col + 1];
            float v0 = acc[mt][nt][0] + b0, v1 = acc[mt][nt][1] + b1;
            float v2 = acc[mt][nt][2] + b0, v3 = acc[mt][nt][3] + b1;
            if (mode == 0) {
                __nv_bfloat16* o = (__nv_bfloat16*)Cout + (long)t * strideCt;
                *(__nv_bfloat162*)(o + rowLo * Nfull + n0 + col) =
                    __floats2bfloat162_rn(fmaxf(v0, 0.f), fmaxf(v1, 0.f));
                *(__nv_bfloat162*)(o + rowHi * Nfull + n0 + col) =
                    __floats2bfloat162_rn(fmaxf(v2, 0.f), fmaxf(v3, 0.f));
            } else if (mode == 1) {
                __nv_bfloat16* o = (__nv_bfloat16*)Cout + (long)t * strideCt;
                *(__nv_bfloat162*)(o + rowLo * Nfull + n0 + col) =
                    __floats2bfloat162_rn(sigmoidf(v0), sigmoidf(v1));
                *(__nv_bfloat162*)(o + rowHi * Nfull + n0 + col) =
                    __floats2bfloat162_rn(sigmoidf(v2), sigmoidf(v3));
            } else {
                if (col < C_) {
                    float* o = (float*)Cout + (long)t * strideCt;
                    *(float2*)(o + rowLo * C_ + col) = make_float2(v0, v1);
                    *(float2*)(o + rowHi * C_ + col) = make_float2(v2, v3);
                }
            }
        }
    }
}

// ---------------------------------------------------------------------------
// elementwise fp32 -> bf16
// ---------------------------------------------------------------------------
__global__ __launch_bounds__(256) void conv_bf16(const float* __restrict__ in,
                                                 __nv_bfloat16* __restrict__ out,
                                                 int n)
{
    int i = blockIdx.x * 256 + threadIdx.x;
    if (i < n) out[i] = __float2bfloat16(in[i]);
}

// ---------------------------------------------------------------------------
// batched transpose + convert: in[t][R][Cc] f32  ->  out[t][Cc][R] bf16
// ---------------------------------------------------------------------------
__global__ __launch_bounds__(256) void transpose_bf16(const float* __restrict__ in,
                                                      __nv_bfloat16* __restrict__ out,
                                                      int R, int Cc)
{
    __shared__ float tile[32][33];
    int t = blockIdx.z;
    in  += (long)t * R * Cc;
    out += (long)t * R * Cc;
    int x = blockIdx.x * 32 + threadIdx.x;
    int y0 = blockIdx.y * 32;
    #pragma unroll
    for (int j = threadIdx.y; j < 32; j += 8)
        tile[j][threadIdx.x] = in[(long)(y0 + j) * Cc + x];
    __syncthreads();
    int xo = y0 + threadIdx.x;
    int yo0 = blockIdx.x * 32;
    #pragma unroll
    for (int j = threadIdx.y; j < 32; j += 8)
        out[(long)(yo0 + j) * R + xo] = __float2bfloat16(tile[threadIdx.x][j]);
}

// ---------------------------------------------------------------------------
// Routing product (bf16 p in, fp32 math, bf16 mu out)
// ---------------------------------------------------------------------------
__global__ __launch_bounds__(512) void mu_kernel(const __nv_bfloat16* __restrict__ p,
                                                 __nv_bfloat16* __restrict__ mub)
{
    int b = blockIdx.x;
    int t = blockIdx.y;
    int l = threadIdx.x;
    __shared__ float ps[L_];

    long base = ((long)t * B_ + b) * L_;
    ps[l] = __bfloat162float(p[base + l]);
    __syncthreads();

    float m = 1.0f;
    #pragma unroll
    for (int d = 0; d <= 8; d++) {
        int node = (1 << d) - 1 + (l >> (9 - d));
        float v = ps[node];
        m *= ((l >> (8 - d)) & 1) ? (1.0f - v) : v;
    }
    mub[base + l] = __float2bfloat16(m);
}

// ---------------------------------------------------------------------------
// softmax over classes with smem-staged transpose.
// grid = (L_/128, T_), block = 256 (8 warps). Each warp computes 16 rows;
// results staged in smem [100][132] then written out coalesced (c-major).
// ---------------------------------------------------------------------------
__global__ __launch_bounds__(256) void softmaxT_kernel(const float* __restrict__ pi,
                                                       __nv_bfloat16* __restrict__ lpT)
{
    __shared__ __nv_bfloat16 tile[C_][132];

    int l0 = blockIdx.x * 128;
    int t  = blockIdx.y;
    int wid = threadIdx.x >> 5;
    int lane = threadIdx.x & 31;

    #pragma unroll 1
    for (int r = 0; r < 16; r++) {
        int lloc = wid * 16 + r;                       // 0..127
        const float* x = pi + ((long)t * L_ + l0 + lloc) * C_;

        float v[4];
        float mx = -1e30f;
        #pragma unroll
        for (int i = 0; i < 4; i++) {
            int c = lane + i * 32;
            v[i] = (c < C_) ? x[c] : -1e30f;
            mx = fmaxf(mx, v[i]);
        }
        #pragma unroll
        for (int o = 16; o > 0; o >>= 1)
            mx = fmaxf(mx, __shfl_xor_sync(0xffffffffu, mx, o));

        float s = 0.0f;
        #pragma unroll
        for (int i = 0; i < 4; i++) {
            int c = lane + i * 32;
            v[i] = (c < C_) ? expf(v[i] - mx) : 0.0f;
            s += v[i];
        }
        #pragma unroll
        for (int o = 16; o > 0; o >>= 1)
            s += __shfl_xor_sync(0xffffffffu, s, o);

        float inv = 1.0f / s;
        #pragma unroll
        for (int i = 0; i < 4; i++) {
            int c = lane + i * 32;
            if (c < C_) tile[c][lloc] = __float2bfloat16(v[i] * inv);
        }
    }
    __syncthreads();

    // coalesced write-out: rows of 128 contiguous bf16
    __nv_bfloat16* o = lpT + (long)t * CP_ * L_ + l0;
    for (int idx = threadIdx.x; idx < C_ * 128; idx += 256) {
        int c = idx >> 7;
        int l = idx & 127;
        o[(long)c * L_ + l] = tile[c][l];
    }
}

// ---------------------------------------------------------------------------
// Deterministic reduce over trees + scale + log
// ---------------------------------------------------------------------------
__global__ __launch_bounds__(256) void finalize_kernel(const float* __restrict__ part,
                                                       float* __restrict__ out)
{
    int i = blockIdx.x * 256 + threadIdx.x;
    if (i >= B_ * C_) return;
    float s = 0.0f;
    #pragma unroll
    for (int t = 0; t < T_; t++) s += part[(long)t * B_ * C_ + i];
    out[i] = logf(s * (1.0f / (float)(L_ * T_)));
}

// ---------------------------------------------------------------------------
extern "C" void kernel_launch(void* const* d_in, const int* in_sizes, int n_in,
                              void* d_out, int out_size)
{
    const float* feat = (const float*)d_in[0];   // [B, F]
    const float* W1   = (const float*)d_in[1];   // [T, F, H]
    const float* b1   = (const float*)d_in[2];   // [T, H]
    const float* W2   = (const float*)d_in[3];   // [T, H, L]
    const float* b2   = (const float*)d_in[4];   // [T, L]
    const float* pi   = (const float*)d_in[5];   // [T, L, C]
    float* out        = (float*)d_out;           // [B, C]

    void *pfb, *pw1t, *pw2t, *phb, *ppb, *pmub, *plpT, *ppart;
    cudaGetSymbolAddress(&pfb,   g_featb);
    cudaGetSymbolAddress(&pw1t,  g_w1t);
    cudaGetSymbolAddress(&pw2t,  g_w2t);
    cudaGetSymbolAddress(&phb,   g_hb);
    cudaGetSymbolAddress(&ppb,   g_pb);
    cudaGetSymbolAddress(&pmub,  g_mub);
    cudaGetSymbolAddress(&plpT,  g_lpT);
    cudaGetSymbolAddress(&ppart, g_part);

    // operand prep
    conv_bf16<<<(B_ * F_ + 255) / 256, 256>>>(feat, (__nv_bfloat16*)pfb, B_ * F_);
    transpose_bf16<<<dim3(H_ / 32, F_ / 32, T_), dim3(32, 8)>>>(
        W1, (__nv_bfloat16*)pw1t, F_, H_);
    transpose_bf16<<<dim3(L_ / 32, H_ / 32, T_), dim3(32, 8)>>>(
        W2, (__nv_bfloat16*)pw2t, H_, L_);
    softmaxT_kernel<<<dim3(L_ / 128, T_), 256>>>(pi, (__nv_bfloat16*)plpT);

    // GEMM1: h = relu(feat @ W1 + b1)  M=1024 N=128 K=512
    gemm_tc<<<dim3(8, 1, T_), 256>>>(
        (const __nv_bfloat16*)pfb, 0L,
        (const __nv_bfloat16*)pw1t, (long)H_ * F_,
        b1, (long)H_,
        phb, (long)B_ * H_,
        F_, H_, /*mode=*/0);

    // GEMM2: p = sigmoid(h @ W2 + b2)  M=1024 N=512 K=128  (bf16 out)
    gemm_tc<<<dim3(8, 4, T_), 256>>>(
        (const __nv_bfloat16*)phb, (long)B_ * H_,
        (const __nv_bfloat16*)pw2t, (long)L_ * H_,
        b2, (long)L_,
        ppb, (long)B_ * L_,
        H_, L_, /*mode=*/1);

    // routing products (bf16 in, bf16 out)
    mu_kernel<<<dim3(B_, T_), 512>>>((const __nv_bfloat16*)ppb, (__nv_bfloat16*)pmub);

    // final contraction per tree: part[t] = mu[t] @ leafpT[t]^T
    gemm_tc<<<dim3(8, 1, T_), 256>>>(
        (const __nv_bfloat16*)pmub, (long)B_ * L_,
        (const __nv_bfloat16*)plpT, (long)CP_ * L_,
        b1 /*unused in mode 2*/, 0L,
        ppart, (long)B_ * C_,
        L_, 0, /*mode=*/2);

    // sum over trees, scale, log
    finalize_kernel<<<(B_ * C_ + 255) / 256, 256>>>((const float*)ppart, out);
}